// round 13
// baseline (speedup 1.0000x reference)
#include <cuda_runtime.h>
#include <math.h>
#include <stdint.h>

#define TT 512
#define BB 128
#define HH 256
#define AA 18
#define BH (BB*HH)
#define NCTA 128

#define OFF_BASE 1179648u
#define OFF_ACT  1245184u
#define OFF_HT   1310720u
#define OFF_CT   1376256u

typedef unsigned long long ull;

static __device__ __align__(16) float g_core[(size_t)TT*BH];  // layer-1 h per step
static __device__ __align__(16) float g_h0buf[2][BH];         // layer-0 h ping-pong
static __device__ __align__(16) float g_nd[TT*BB];            // float not-done mask
static __device__ __align__(128) unsigned g_flags[NCTA];      // per-CTA arrival flags
static __device__ int g_mode;

// ---------------- packed f32x2 + sync helpers ----------------
__device__ __forceinline__ ull ffma2(ull a, ull b, ull c){
    ull d;
    asm("fma.rn.f32x2 %0,%1,%2,%3;" : "=l"(d) : "l"(a), "l"(b), "l"(c));
    return d;
}
__device__ __forceinline__ float hsum2(ull v){
    float lo, hi;
    asm("mov.b64 {%0,%1},%2;" : "=f"(lo), "=f"(hi) : "l"(v));
    return lo + hi;
}
__device__ __forceinline__ ull pack2(float lo, float hi){
    ull r;
    asm("mov.b64 %0,{%1,%2};" : "=l"(r) : "f"(lo), "f"(hi));
    return r;
}
__device__ __forceinline__ float sigf(float x){ return 1.0f/(1.0f+__expf(-x)); }
__device__ __forceinline__ float tanhe(float x){ return 1.0f - 2.0f/(__expf(2.0f*x)+1.0f); }

__device__ __forceinline__ unsigned ld_acq(const unsigned* p){
    unsigned v;
    asm volatile("ld.acquire.gpu.u32 %0,[%1];" : "=r"(v) : "l"(p));
    return v;
}
__device__ __forceinline__ void st_rel(unsigned* p, unsigned v){
    asm volatile("st.release.gpu.u32 [%0],%1;" :: "l"(p), "r"(v));
}
__device__ __forceinline__ void stcg1(float* p, float v){ __stcg(p, v); }

// Group barrier over the 32 CTAs sharing this CTA's batch rows.
// Arrival: fence + st.release to own flag. Wait: warp 0 polls all 32 group
// flags directly (one per lane). Post-wait __threadfence() invalidates L1
// so the fresh h values (written via st.cg by peer CTAs) are re-fetched.
__device__ __forceinline__ void gsync(unsigned target, int bx){
    __syncthreads();
    if (threadIdx.x < 32){
        const int base = bx & ~31;
        if (threadIdx.x == 0){ __threadfence(); st_rel(&g_flags[bx], target); }
        unsigned v;
        do { v = ld_acq(&g_flags[base + threadIdx.x]); }
        while (!__all_sync(0xFFFFFFFFu, v >= target));
        if (threadIdx.x == 0) __threadfence();   // CCTL.IVALL: drop stale L1 lines
    }
    __syncthreads();
}

// ---- classify 'done' wire dtype; also reset barrier state ----
__global__ void detect_kernel(const unsigned* __restrict__ dw){
    __shared__ int s[5];
    if (threadIdx.x < 5) s[threadIdx.x] = 0;
    if (threadIdx.x < NCTA) g_flags[threadIdx.x] = 0;
    __syncthreads();
    int anynz=0, badf=0, badi=0, badb=0, mix=0;
    for (int i = threadIdx.x; i < 16384; i += 256){
        unsigned w = dw[i];
        if (w) anynz = 1;
        if (w != 0u && w != 0x3F800000u) badf = 1;
        if (w > 1u) badi = 1;
        unsigned h0 = w & 0xFFFFu, h1 = w >> 16;
        if ((h0 && h0 != 0x3F80u) || (h1 && h1 != 0x3F80u)) badb = 1;
        if (w == 0x00003F80u || w == 0x3F803F80u) mix = 1;
    }
    if (anynz) atomicOr(&s[0],1);
    if (badf)  atomicOr(&s[1],1);
    if (badi)  atomicOr(&s[2],1);
    if (badb)  atomicOr(&s[3],1);
    if (mix)   atomicOr(&s[4],1);
    __syncthreads();
    if (threadIdx.x == 0){
        int m;
        if (!s[0]) m = 0;
        else if (!s[3] && s[4]) m = 3;
        else if (!s[1]) m = 2;
        else if (!s[2]) m = 1;
        else m = 0;
        g_mode = m;
    }
}

__global__ void convert_kernel(const void* __restrict__ dptr){
    int i = blockIdx.x*256 + threadIdx.x;
    int m = g_mode; int v;
    if (m == 0)      v = ((const unsigned char*) dptr)[i] != 0;
    else if (m == 1) v = ((const int*)           dptr)[i] != 0;
    else if (m == 2) v = ((const float*)         dptr)[i] != 0.0f;
    else             v = ((const unsigned short*)dptr)[i] != 0;
    g_nd[i] = v ? 0.0f : 1.0f;
}

// Fold-exchange: halve the live accumulator set while butterflying lanes.
__device__ __forceinline__ float foldx(float x, float y, bool hi, int off){
    float mine = hi ? y : x;
    float send = hi ? x : y;
    return mine + __shfl_xor_sync(0xFFFFFFFFu, send, off);
}

// ------ one LSTM layer: this warp = 1 hidden unit (4 gates), 32 rows ------
// lane l covers k-quads at {0,128,256,384}+4l of the 512-dim [x|h] vector.
// Partial gate sums land in sp[(r*8+u)*4 + g].
__device__ __forceinline__ void row_phase(
    const float* __restrict__ wsl,   // layer base: [32 unitgates][512]
    const float* __restrict__ xin,   // [BB][256] current input (unmasked)
    const float* __restrict__ hin,   // [BB][256] recurrent h (masked)
    const float* __restrict__ nd,    // [BB]
    float* __restrict__ sp,
    int lane, int u, int rowg0)
{
    ulonglong2 W[4][4];              // 64 regs
#pragma unroll
    for (int g = 0; g < 4; g++){
        const float* wp = wsl + (u*4 + g)*512 + 4*lane;
#pragma unroll
        for (int q = 0; q < 4; q++) W[g][q] = *(const ulonglong2*)(wp + q*128);
    }
    const bool h16 = (lane & 16) != 0;
    const bool h8  = (lane & 8)  != 0;
    const bool dep = (lane & 7) == 0;
    const int  gw  = lane >> 3;
    const ull z = 0ull;

#pragma unroll 4
    for (int r = 0; r < 32; r++){
        const int rowg = rowg0 + r;
        const float* xp = xin + rowg*256 + 4*lane;
        const float* hp = hin + rowg*256 + 4*lane;
        ulonglong2 x0 = *(const ulonglong2*)(xp);
        ulonglong2 x1 = *(const ulonglong2*)(xp + 128);
        ulonglong2 hh0 = *(const ulonglong2*)(hp);
        ulonglong2 hh1 = *(const ulonglong2*)(hp + 128);
        const ull m2 = pack2(nd[rowg], nd[rowg]);
        ull hm0 = ffma2(hh0.x, m2, z);
        ull hm1 = ffma2(hh0.y, m2, z);
        ull hm2 = ffma2(hh1.x, m2, z);
        ull hm3 = ffma2(hh1.y, m2, z);
        float v[4];
#pragma unroll
        for (int g = 0; g < 4; g++){
            ull a;
            a = ffma2(x0.x, W[g][0].x, z);
            a = ffma2(x0.y, W[g][0].y, a);
            a = ffma2(x1.x, W[g][1].x, a);
            a = ffma2(x1.y, W[g][1].y, a);
            a = ffma2(hm0,  W[g][2].x, a);
            a = ffma2(hm1,  W[g][2].y, a);
            a = ffma2(hm2,  W[g][3].x, a);
            a = ffma2(hm3,  W[g][3].y, a);
            v[g] = hsum2(a);
        }
        float t0 = foldx(v[0], v[2], h16, 16);
        float t1 = foldx(v[1], v[3], h16, 16);
        float rr = foldx(t0, t1, h8, 8);
        rr += __shfl_xor_sync(0xFFFFFFFFu, rr, 4);
        rr += __shfl_xor_sync(0xFFFFFFFFu, rr, 2);
        rr += __shfl_xor_sync(0xFFFFFFFFu, rr, 1);
        if (dep) sp[(r*8 + u)*4 + gw] = rr;
    }
}

__global__ void __launch_bounds__(256,1) scan_kernel(
    const float* __restrict__ x,   const float* __restrict__ h0in,
    const float* __restrict__ c0in,
    const float* __restrict__ wih, const float* __restrict__ whh,
    const float* __restrict__ bih, const float* __restrict__ bhh,
    float* __restrict__ out)
{
    extern __shared__ __align__(16) float sm[];
    float* ws = sm;              // [2][32][512] = 32768 floats (128KB)
    float* sp = sm + 32768;      // [32 rows][8 units][4 gates] = 1024 floats
    float* bs = sm + 33792;      // [2][32]
    const int tid = threadIdx.x, bx = blockIdx.x;
    const int lane = tid & 31, w = tid >> 5;
    const int bgrp = bx >> 5, ugrp = bx & 31;
    const int rowg0 = bgrp * 32;

    // stage weights: ws[l][u*4+g][k]  (k<256: w_ih, k>=256: w_hh), unit u local
    for (int i = tid; i < 32768; i += 256){
        int l = i >> 14, rr = i & 16383, ug = rr >> 9, k = rr & 511;
        int row = (ug & 3)*256 + ugrp*8 + (ug >> 2);
        float v = (k < 256) ? wih[((l<<10)+row)*256 + k] : whh[((l<<10)+row)*256 + k - 256];
        ws[(l*32 + ug)*512 + k] = v;
    }
    if (tid < 64){
        int l = tid >> 5, ug = tid & 31;
        int row = (ug & 3)*256 + ugrp*8 + (ug >> 2);
        bs[l*32 + ug] = bih[(l<<10)+row] + bhh[(l<<10)+row];
    }
    // owner state: tid -> (row = tid>>3 local, unit = tid&7)
    const int orow = rowg0 + (tid >> 3);
    const int oj = ugrp*8 + (tid & 7);
    const int obase = (tid >> 3)*32 + (tid & 7)*4;   // sp offset (floats)
    stcg1(&g_h0buf[0][orow*256 + oj], h0in[orow*256 + oj]);
    float c0own = c0in[orow*256 + oj];
    float c1own = c0in[BH + orow*256 + oj];
    float h0own = 0.0f, h1own = 0.0f;
    __syncthreads();
    gsync(1, bx);

    int pp = 0;
    for (int t = 0; t < TT; t++){
        const float* nd = g_nd + t*BB;
        // ---- layer 0: x(t) + masked h0(t-1) ----
        row_phase(ws, x + (size_t)t*BH, g_h0buf[pp], nd, sp, lane, w, rowg0);
        __syncthreads();
        {
            float4 A = *(const float4*)&sp[obase];
            float m = nd[orow];
            int u4 = (tid & 7)*4;
            float gi = A.x + bs[u4+0];
            float gf = A.y + bs[u4+1];
            float gg = A.z + bs[u4+2];
            float go = A.w + bs[u4+3];
            c0own = sigf(gf)*(c0own*m) + sigf(gi)*tanhe(gg);
            h0own = sigf(go)*tanhe(c0own);
            stcg1(&g_h0buf[pp^1][orow*256 + oj], h0own);
        }
        gsync((unsigned)(t + 2), bx);
        // prefetch this group's x(t+1) block into L2 (8 lines per CTA)
        if (t + 1 < TT && tid < 8){
            const char* nx = (const char*)(x + (size_t)(t+1)*BH + rowg0*256)
                             + (size_t)(ugrp*8 + tid)*128;
            asm volatile("prefetch.global.L2 [%0];" :: "l"(nx));
        }
        // ---- layer 1: h0(t) + masked h1(t-1) ----
        const float* h1src = t ? (g_core + (size_t)(t-1)*BH) : (h0in + BH);
        row_phase(ws + 16384, g_h0buf[pp^1], h1src, nd, sp, lane, w, rowg0);
        __syncthreads();
        {
            float4 A = *(const float4*)&sp[obase];
            float m = nd[orow];
            int u4 = 32 + (tid & 7)*4;
            float gi = A.x + bs[u4+0];
            float gf = A.y + bs[u4+1];
            float gg = A.z + bs[u4+2];
            float go = A.w + bs[u4+3];
            c1own = sigf(gf)*(c1own*m) + sigf(gi)*tanhe(gg);
            h1own = sigf(go)*tanhe(c1own);
            stcg1(&g_core[(size_t)t*BH + orow*256 + oj], h1own);
        }
        __syncthreads();   // protect sp before next step's row_phase writes
        pp ^= 1;
    }
    out[OFF_HT +      orow*256 + oj] = h0own;
    out[OFF_HT + BH + orow*256 + oj] = h1own;
    out[OFF_CT +      orow*256 + oj] = c0own;
    out[OFF_CT + BH + orow*256 + oj] = c1own;
}

__global__ void __launch_bounds__(256) head_kernel(
    const float* __restrict__ Wp, const float* __restrict__ bp,
    const float* __restrict__ Wb, const float* __restrict__ bb,
    float* __restrict__ out)
{
    __shared__ float sw[19*256];
    for (int i = threadIdx.x; i < 19*256; i += 256)
        sw[i] = (i < 18*256) ? Wp[i] : Wb[i - 18*256];
    __syncthreads();
    int warp = (blockIdx.x*blockDim.x + threadIdx.x) >> 5;
    int lane = threadIdx.x & 31;
    if (warp >= TT*BB) return;
    const float* cr = g_core + (size_t)warp*256;
    float acc[19];
#pragma unroll
    for (int a = 0; a < 19; a++) acc[a] = 0.0f;
#pragma unroll
    for (int k0 = 0; k0 < 8; k0++){
        float v = cr[k0*32 + lane];
#pragma unroll
        for (int a = 0; a < 19; a++) acc[a] += v * sw[a*256 + k0*32 + lane];
    }
#pragma unroll
    for (int a = 0; a < 19; a++)
        for (int o = 16; o > 0; o >>= 1) acc[a] += __shfl_xor_sync(0xFFFFFFFFu, acc[a], o);
    if (lane == 0){
        float best = -3.0e38f; int bi = 0;
        for (int a = 0; a < 18; a++){
            float lg = acc[a] + bp[a];
            out[(size_t)warp*AA + a] = lg;
            if (lg > best){ best = lg; bi = a; }
        }
        out[OFF_BASE + warp] = acc[18] + bb[0];
        out[OFF_ACT  + warp] = (float)bi;
    }
}

extern "C" void kernel_launch(void* const* d_in, const int* in_sizes, int n_in,
                              void* d_out, int out_size){
    const float* x    = (const float*)d_in[0];
    const void*  done = d_in[1];
    const float* h0   = (const float*)d_in[2];
    const float* c0   = (const float*)d_in[3];
    const float* wih  = (const float*)d_in[4];
    const float* whh  = (const float*)d_in[5];
    const float* bih  = (const float*)d_in[6];
    const float* bhh  = (const float*)d_in[7];
    const float* Wp   = (const float*)d_in[8];
    const float* bp   = (const float*)d_in[9];
    const float* Wb   = (const float*)d_in[10];
    const float* bb   = (const float*)d_in[11];
    float* out = (float*)d_out;

    const int SMEM_BYTES = (32768 + 1024 + 64) * 4;   // 135424
    cudaFuncSetAttribute(scan_kernel, cudaFuncAttributeMaxDynamicSharedMemorySize, SMEM_BYTES);

    detect_kernel<<<1, 256>>>((const unsigned*)done);
    convert_kernel<<<256, 256>>>(done);
    scan_kernel<<<NCTA, 256, SMEM_BYTES>>>(x, h0, c0, wih, whh, bih, bhh, out);
    head_kernel<<<8192, 256>>>(Wp, bp, Wb, bb, out);
}